// round 12
// baseline (speedup 1.0000x reference)
#include <cuda_runtime.h>
#include <cstdint>

// Problem constants
#define T_LEN 2048
#define BATCH 32
#define HID   256
#define G3    768
#define NSCAN 128          // 8 domains x 16 blocks
#define NDOM  8
#define BPD   16
#define RPD   4            // batch rows per domain
#define NTOT  148
#define NWORK (NTOT - NSCAN)   // 20 gemm workers
#define NTILE 8192

typedef unsigned long long ull;

// ---------------------------------------------------------------------------
// Device scratch
// ---------------------------------------------------------------------------
__device__ float g_X[(size_t)T_LEN * BATCH * 512];   // [m=t*32+b][c 512]
__device__ float g_h0[4][NDOM][HID * RPD];           // 4-deep ring, [k*4+r]
__device__ float g_h1[2][NDOM][HID * RPD];           // 2-deep ring
__device__ unsigned g_flag[256 * 8];                 // [0..127]=A, [128..255]=B
__device__ unsigned g_tcnt[T_LEN / 2];
__device__ unsigned g_run;

// ---------------------------------------------------------------------------
__device__ __forceinline__ ull pack2(float v) {
    ull r; asm("mov.b64 %0, {%1, %1};" : "=l"(r) : "f"(v)); return r;
}
__device__ __forceinline__ void fma2(ull& d, ull a, ull b) {
    asm("fma.rn.f32x2 %0, %1, %2, %0;" : "+l"(d) : "l"(a), "l"(b));
}
__device__ __forceinline__ void unpack2(ull v, float& lo, float& hi) {
    asm("mov.b64 {%0, %1}, %2;" : "=f"(lo), "=f"(hi) : "l"(v));
}
__device__ __forceinline__ void poll_ge(const unsigned* addr, unsigned target) {
    unsigned v;
    do {
        asm volatile("ld.acquire.gpu.global.u32 %0, [%1];"
                     : "=r"(v) : "l"(addr) : "memory");
    } while ((int)(v - target) < 0);
}
__device__ __forceinline__ void barA() {
    asm volatile("bar.sync 1, 128;" ::: "memory");
}
__device__ __forceinline__ void barB() {
    asm volatile("bar.sync 2, 128;" ::: "memory");
}

// ---------------------------------------------------------------------------
// GEMM worker: grid-strided 64x64x256 tiles; g_X = input@Wih0[:,:512]+b0
// ---------------------------------------------------------------------------
__device__ void gemm_worker(int wb, const float* __restrict__ A,
                            const float* __restrict__ W,
                            const float* __restrict__ bias,
                            float* smem, int Lmax)
{
    float (*As)[65] = (float(*)[65])smem;
    float (*Bs)[64] = (float(*)[64])(smem + 32 * 65);

    const int tid = threadIdx.x;
    const int tx  = tid & 15;
    const int ty  = tid >> 4;
    const int ar  = tid >> 2;
    const int ak  = (tid & 3) * 8;
    const int bk  = tid >> 3;
    const int bc  = (tid & 7) * 8;

    for (int n = wb; n < NTILE; n += NWORK) {
        const int bx = n >> 3;
        if (2 * bx >= Lmax) break;
        const int m0 = bx * 64;
        const int n0 = (n & 7) * 64;

        ull acc2[4][2];
#pragma unroll
        for (int i = 0; i < 4; i++) { acc2[i][0] = 0ull; acc2[i][1] = 0ull; }

        for (int k0 = 0; k0 < 256; k0 += 32) {
            float4 a0  = *(const float4*)&A[(size_t)(m0 + ar) * 256 + k0 + ak];
            float4 a1  = *(const float4*)&A[(size_t)(m0 + ar) * 256 + k0 + ak + 4];
            float4 b0v = *(const float4*)&W[(size_t)(k0 + bk) * G3 + n0 + bc];
            float4 b1v = *(const float4*)&W[(size_t)(k0 + bk) * G3 + n0 + bc + 4];

            As[ak + 0][ar] = a0.x; As[ak + 1][ar] = a0.y;
            As[ak + 2][ar] = a0.z; As[ak + 3][ar] = a0.w;
            As[ak + 4][ar] = a1.x; As[ak + 5][ar] = a1.y;
            As[ak + 6][ar] = a1.z; As[ak + 7][ar] = a1.w;
            *(float4*)&Bs[bk][bc]     = b0v;
            *(float4*)&Bs[bk][bc + 4] = b1v;
            __syncthreads();

#pragma unroll
            for (int kk = 0; kk < 32; kk++) {
                const ulonglong2 bq = *(const ulonglong2*)&Bs[kk][ty * 4];
#pragma unroll
                for (int ri = 0; ri < 4; ri++) {
                    const ull av = pack2(As[kk][tx * 4 + ri]);
                    fma2(acc2[ri][0], bq.x, av);
                    fma2(acc2[ri][1], bq.y, av);
                }
            }
            __syncthreads();
        }

        const float4 bv = *(const float4*)&bias[n0 + ty * 4];
#pragma unroll
        for (int ri = 0; ri < 4; ri++) {
            float4 v;
            unpack2(acc2[ri][0], v.x, v.y);
            unpack2(acc2[ri][1], v.z, v.w);
            v.x += bv.x; v.y += bv.y; v.z += bv.z; v.w += bv.w;
            *(float4*)&g_X[(size_t)(m0 + tx * 4 + ri) * 512 + n0 + ty * 4] = v;
        }

        __threadfence();
        __syncthreads();
        if (tid == 0) {
            asm volatile("red.release.gpu.global.add.u32 [%0], %1;"
                         :: "l"(&g_tcnt[bx]), "r"(1u) : "memory");
        }
    }
}

// ---------------------------------------------------------------------------
// ONE kernel, 148 blocks (1/SM):
//   blocks 0..127: scan; 8 domains x 16 blocks; block owns 16 h-cols.
//     Warps 4-7 = A-pipeline (layer 0, recurrence critical path, hi priority).
//     Warps 0-3 = B-pipeline (layer 1), independent cadence, own flag set.
//   blocks 128..147: gemm workers.
// A round a: h0(a) = f(h0(a-1), g_X row a).     Publishes A-flag = a+1.
// B round b: h1(b) = f(h1(b-1), h0(b)).         Publishes B-flag = b+1.
// A backpressure: h0 ring is 4 deep; A round a polls peers' B-flag >= a-3.
// ---------------------------------------------------------------------------
__global__ __launch_bounds__(256, 1) void fused_all(
    const float* __restrict__ input,
    const float* __restrict__ Whh0,
    const float* __restrict__ Whh1,
    const float* __restrict__ Wih0,
    const float* __restrict__ Wih1,
    const float* __restrict__ b0,
    const float* __restrict__ b1,
    const int*   __restrict__ length,
    float* __restrict__ out1,
    float* __restrict__ hn)
{
    extern __shared__ float smem[];
    const int bid = blockIdx.x;
    const int tid = threadIdx.x;

    int Lmax = 0;
#pragma unroll 8
    for (int r = 0; r < BATCH; r++) Lmax = max(Lmax, length[r]);

    if (bid >= NSCAN) {
        gemm_worker(bid - NSCAN, input, Wih0, b0, smem, Lmax);
        return;
    }

    // smem layout
    float4* hsA4 = (float4*)smem;            // [256] float4  (4KB)
    float4* hsB4 = hsA4 + 256;               // [512] float4  (8KB)
    float*  redA = (float*)(hsB4 + 512);     // [4q][32p][4r] (2KB)
    float*  redB = redA + 512;               // (2KB)
    float*  outs = redB + 512;               // [4r][16j]

    const int d   = bid >> 4;
    const int c0  = (bid & 15) * 16;

    int Ld = 0;
#pragma unroll
    for (int r = 0; r < RPD; r++) Ld = max(Ld, length[4 * d + r]);

    const unsigned R   = *(volatile unsigned*)&g_run;
    const unsigned fbA = R * (unsigned)Ld;
    const unsigned fbB = R * (unsigned)Ld;
    const unsigned tb  = R * 8u;

    const int lane = tid & 31;
    const int pc   = (lane < 16) ? (c0 + lane) : (256 + c0 + lane - 16);

    if (tid >= 128) {
        // =================== A-pipeline: layer 0 ===================
        const int atid = tid - 128;
        const int wq   = (tid >> 5) - 4;

        float wA[64];
#pragma unroll
        for (int kk = 0; kk < 64; kk++)
            wA[kk] = Whh0[(size_t)(wq * 64 + kk) * G3 + pc];

        const bool isg = (atid < 64);
        const int  gj  = atid >> 2;
        const int  gr  = atid & 3;
        const int  glen = length[4 * d + (atid & 3)];
        float hcur = 0.f;
        int rdy = 0;

        for (int a = 0; a < Ld; a++) {
            if (a > 0 && atid < 16)
                poll_ge(&g_flag[(d * 16 + atid) * 8], fbA + (unsigned)a);
            if (a >= 4 && atid >= 16 && atid < 32)
                poll_ge(&g_flag[(128 + d * 16 + atid - 16) * 8],
                        fbB + (unsigned)(a - 3));
            if (atid == 32 && (a >> 1) >= rdy) {
                poll_ge(&g_tcnt[a >> 1], tb + 8u);
                rdy = (a >> 1) + 1;
            }
            barA();

            float xh = 0.f, xt = 0.f;
            if (isg) {
                const size_t m = (size_t)a * BATCH + 4 * d + gr;
                xh = __ldg(&g_X[m * 512 + c0 + gj]);
                xt = __ldg(&g_X[m * 512 + 256 + c0 + gj]);
            }
            if (a > 0) {
                const float4* s = (const float4*)g_h0[(a - 1) & 3][d];
                hsA4[atid]       = __ldcg(s + atid);
                hsA4[128 + atid] = __ldcg(s + 128 + atid);
            } else {
                const float4 z = make_float4(0.f, 0.f, 0.f, 0.f);
                hsA4[atid] = z; hsA4[128 + atid] = z;
            }
            barA();

            ull a0 = 0ull, a1 = 0ull;
#pragma unroll
            for (int kk = 0; kk < 64; kk++) {
                const ulonglong2 hv = *(const ulonglong2*)&hsA4[wq * 64 + kk];
                const ull w2 = pack2(wA[kk]);
                fma2(a0, hv.x, w2);
                fma2(a1, hv.y, w2);
            }
            { ulonglong2 st2; st2.x = a0; st2.y = a1;
              *(ulonglong2*)&redA[(wq * 32 + lane) * 4] = st2; }
            barA();

            if (isg) {
                float sh = 0.f, st = 0.f;
#pragma unroll
                for (int q = 0; q < 4; q++) {
                    sh += redA[(q * 32 + gj) * 4 + gr];
                    st += redA[(q * 32 + gj + 16) * 4 + gr];
                }
                const float ph = sh + xh;
                const float pt = st + xt;
                const float tg = 1.f / (1.f + __expf(-pt));
                const float cg = 1.f / (1.f + __expf(-tg));  // bug-faithful
                const float sv = tanhf(ph) * tg + hcur * cg;
                const float hnew = (a < glen) ? sv : hcur;
                hcur = hnew;
                __stcg(&g_h0[a & 3][d][c0 * 4 + atid], hnew);
            }
            barA();

            if (atid == 0) {
                asm volatile("st.release.gpu.global.u32 [%0], %1;"
                             :: "l"(&g_flag[bid * 8]),
                                "r"(fbA + (unsigned)(a + 1)) : "memory");
            }
        }
        if (isg) hn[(4 * d + gr) * HID + c0 + gj] = hcur;

    } else {
        // =================== B-pipeline: layer 1 ===================
        const int wq = tid >> 5;

        float wB[128];
#pragma unroll
        for (int kk = 0; kk < 128; kk++) {
            const int k = wq * 128 + kk;
            wB[kk] = (k < 256) ? Whh1[(size_t)k * G3 + pc]
                               : Wih1[(size_t)(k - 256) * G3 + pc];
        }

        const bool isg = (tid < 64);
        const int  gj  = tid >> 2;
        const int  gr  = tid & 3;
        const int  glen = length[4 * d + (tid & 3)];
        float gbh = 0.f, gbt = 0.f;
        if (isg) { gbh = b1[c0 + gj]; gbt = b1[256 + c0 + gj]; }
        if (tid < 64) outs[tid] = 0.f;
        float hcur = 0.f;

        for (int b = 0; b < Ld; b++) {
            if (b > 0 && tid < 16)
                poll_ge(&g_flag[(128 + d * 16 + tid) * 8], fbB + (unsigned)b);
            if (tid >= 16 && tid < 32)
                poll_ge(&g_flag[(d * 16 + tid - 16) * 8], fbA + (unsigned)(b + 1));
            barB();

            if (b > 0) {
                const float4* s1 = (const float4*)g_h1[(b - 1) & 1][d];
                hsB4[tid]       = __ldcg(s1 + tid);
                hsB4[128 + tid] = __ldcg(s1 + 128 + tid);
            } else {
                const float4 z = make_float4(0.f, 0.f, 0.f, 0.f);
                hsB4[tid] = z; hsB4[128 + tid] = z;
            }
            {
                const float4* s0 = (const float4*)g_h0[b & 3][d];
                hsB4[256 + tid] = __ldcg(s0 + tid);
                hsB4[384 + tid] = __ldcg(s0 + 128 + tid);
            }
            barB();

            ull a0 = 0ull, a1 = 0ull;
#pragma unroll
            for (int kk = 0; kk < 128; kk++) {
                const ulonglong2 hv = *(const ulonglong2*)&hsB4[wq * 128 + kk];
                const ull w2 = pack2(wB[kk]);
                fma2(a0, hv.x, w2);
                fma2(a1, hv.y, w2);
            }
            { ulonglong2 st2; st2.x = a0; st2.y = a1;
              *(ulonglong2*)&redB[(wq * 32 + lane) * 4] = st2; }
            barB();

            if (isg) {
                float sh = 0.f, st = 0.f;
#pragma unroll
                for (int q = 0; q < 4; q++) {
                    sh += redB[(q * 32 + gj) * 4 + gr];
                    st += redB[(q * 32 + gj + 16) * 4 + gr];
                }
                const float ph = sh + gbh;
                const float pt = st + gbt;
                const float tg = 1.f / (1.f + __expf(-pt));
                const float cg = 1.f / (1.f + __expf(-tg));  // bug-faithful
                const float sv = tanhf(ph) * tg + hcur * cg;
                const float hnew = (b < glen) ? sv : hcur;
                hcur = hnew;
                __stcg(&g_h1[b & 1][d][c0 * 4 + tid], hnew);
            }
            barB();

            if (tid == 0) {
                asm volatile("st.release.gpu.global.u32 [%0], %1;"
                             :: "l"(&g_flag[(128 + bid) * 8]),
                                "r"(fbB + (unsigned)(b + 1)) : "memory");
            }
            // out1 write off the critical path (post-publish)
            if (isg)
                out1[((size_t)b * BATCH + 4 * d + gr) * HID + c0 + gj] = hcur;
        }

        // epilogue: hn1 + frozen-tail fill
        if (isg) {
            hn[BATCH * HID + (4 * d + gr) * HID + c0 + gj] = hcur;
            outs[gr * 16 + gj] = hcur;
        }
        barB();
        {
            const int nfill = (T_LEN - Ld) * 16;   // float4 units
            for (int idx = tid; idx < nfill; idx += 128) {
                const int t  = Ld + (idx >> 4);
                const int rr = (idx >> 2) & 3;
                const int jj = idx & 3;
                *(float4*)&out1[((size_t)t * BATCH + 4 * d + rr) * HID
                                + c0 + jj * 4] =
                    *(const float4*)&outs[rr * 16 + jj * 4];
            }
        }
        if (bid == 0 && tid == 0) *(volatile unsigned*)&g_run = R + 1u;
    }
}

// ---------------------------------------------------------------------------
extern "C" void kernel_launch(void* const* d_in, const int* in_sizes, int n_in,
                              void* d_out, int out_size) {
    const float* input  = (const float*)d_in[0];
    const int*   length = (const int*)d_in[1];
    const float* Wih0   = (const float*)d_in[2];
    const float* Whh0   = (const float*)d_in[3];
    const float* b0     = (const float*)d_in[4];
    const float* Wih1   = (const float*)d_in[5];
    const float* Whh1   = (const float*)d_in[6];
    const float* b1     = (const float*)d_in[7];

    float* out1 = (float*)d_out;
    float* hn   = (float*)d_out + (size_t)T_LEN * BATCH * HID;

    // scan: (256+512)*16 + 2KB + 2KB + 256B ; worker: 16.5KB -> take max
    const int smem_bytes = (256 * 4 + 512 * 4 + 512 + 512 + 64) * 4;
    static bool attr_set = false;
    if (!attr_set) {
        cudaFuncSetAttribute(fused_all, cudaFuncAttributeMaxDynamicSharedMemorySize,
                             smem_bytes);
        attr_set = true;
    }

    fused_all<<<NTOT, 256, smem_bytes>>>(
        input, Whh0, Whh1, Wih0, Wih1, b0, b1, length, out1, hn);
}